// round 8
// baseline (speedup 1.0000x reference)
#include <cuda_runtime.h>
#include <cuda_bf16.h>
#include <math.h>
#include <stdint.h>

#define NNODES 50000
#define KNEI   32
#define DIM    128
#define DOUT   128
#define KTOT   512
#define BM     128
#define BK     32

// gemm1 (fp32 A) smem geometry
#define SSTR   36                    // A row stride (u32), 144 B (16B-mult)
#define BSTR   136                   // B row stride (u32), [k][n], 544 B
#define A_U32  (BM * SSTR)           // 4608
#define B_U32  (BK * BSTR)           // 4352
#define STG1_U32 (A_U32 + B_U32)     // 8960

// gemm2 (bf16 A) smem geometry
#define A2STR  24                    // bf16 A row stride (u32), 96 B (16B-mult)
#define A2_U32 (BM * A2STR)          // 3072
#define STG2_U32 (A2_U32 + B_U32)    // 7424

// Static device scratch (allowed).
__device__ __nv_bfloat16 g_f1b[(size_t)NNODES * DIM];   // bf16(fea1)
__device__ __nv_bfloat16 g_n1b[(size_t)NNODES * DIM];   // bf16(mean nei1)
__device__ __nv_bfloat16 g_n2b[(size_t)NNODES * DIM];   // bf16(mean nei2)
__device__ uint32_t g_Wt [(size_t)KTOT * DOUT];         // tf32(W), [k][n]
__device__ float    g_part[(size_t)NNODES * DOUT];      // fp32 partial (f-half)

__device__ __forceinline__ uint32_t f2tf32(float f) {
    uint32_t u;
    asm("cvt.rna.tf32.f32 %0, %1;" : "=r"(u) : "f"(f));
    return u;
}
__device__ __forceinline__ uint32_t smem_u32p(const void* p) {
    uint32_t a;
    asm("{ .reg .u64 t; cvta.to.shared.u64 t, %1; cvt.u32.u64 %0, t; }" : "=r"(a) : "l"(p));
    return a;
}
__device__ __forceinline__ void cp_async16(uint32_t dst, const void* src) {
    asm volatile("cp.async.cg.shared.global [%0], [%1], 16;"
                 :: "r"(dst), "l"(src) : "memory");
}
#define CP_COMMIT() asm volatile("cp.async.commit_group;" ::: "memory")
#define CP_WAIT0()  asm volatile("cp.async.wait_group 0;"  ::: "memory")

__device__ __forceinline__ void mma_tf32(float c[4], const uint32_t a[4],
                                         const uint32_t b[2]) {
    asm volatile(
        "mma.sync.aligned.m16n8k8.row.col.f32.tf32.tf32.f32 "
        "{%0,%1,%2,%3}, {%4,%5,%6,%7}, {%8,%9}, {%0,%1,%2,%3};"
        : "+f"(c[0]), "+f"(c[1]), "+f"(c[2]), "+f"(c[3])
        : "r"(a[0]), "r"(a[1]), "r"(a[2]), "r"(a[3]), "r"(b[0]), "r"(b[1]));
}

// ---------------------------------------------------------------------------
// Kernel 1 (conv): fea1 -> bf16 ; W -> tf32 [k][n].
// ---------------------------------------------------------------------------
__global__ __launch_bounds__(256)
void conv_kernel(const float* __restrict__ fea1, const float* __restrict__ W) {
    const int t = blockIdx.x * 256 + threadIdx.x;   // 0..799999
    {
        float4 a = reinterpret_cast<const float4*>(fea1)[2 * (size_t)t];
        float4 b = reinterpret_cast<const float4*>(fea1)[2 * (size_t)t + 1];
        __nv_bfloat162 p0 = __floats2bfloat162_rn(a.x, a.y);
        __nv_bfloat162 p1 = __floats2bfloat162_rn(a.z, a.w);
        __nv_bfloat162 p2 = __floats2bfloat162_rn(b.x, b.y);
        __nv_bfloat162 p3 = __floats2bfloat162_rn(b.z, b.w);
        uint4 o;
        o.x = *reinterpret_cast<uint32_t*>(&p0);
        o.y = *reinterpret_cast<uint32_t*>(&p1);
        o.z = *reinterpret_cast<uint32_t*>(&p2);
        o.w = *reinterpret_cast<uint32_t*>(&p3);
        reinterpret_cast<uint4*>(g_f1b)[t] = o;
    }
    if (t < (KTOT * DOUT) / 4) {
        float4 w = reinterpret_cast<const float4*>(W)[t];
        uint4 o;
        o.x = f2tf32(w.x); o.y = f2tf32(w.y); o.z = f2tf32(w.z); o.w = f2tf32(w.w);
        reinterpret_cast<uint4*>(g_Wt)[t] = o;
    }
}

// ---------------------------------------------------------------------------
// Kernel 2 (mixed): bid%17==0 -> gemm1 role (391 CTAs): partial = [f1|f2]@W[0:256]
//                   else       -> agg role (6250 CTAs): bf16 gather means
// ---------------------------------------------------------------------------
__global__ __launch_bounds__(256, 2)
void mixed_kernel(const float* __restrict__ fea1,
                  const float* __restrict__ fea2,
                  const int*   __restrict__ idx1,
                  const int*   __restrict__ idx2) {
    extern __shared__ uint32_t smem[];
    const int bid = blockIdx.x;
    const int tid = threadIdx.x;
    const int lane = tid & 31;

    if (bid % 17 == 0) {
        // ================= gemm1 role =================
        const int g = bid / 17;                 // 0..390
        const int wid  = tid >> 5;
        const int gid  = lane >> 2;
        const int tig  = lane & 3;
        const int warp_m = (wid >> 2) * 64;
        const int warp_n = (wid & 3) * 32;
        const int block_row = g * BM;
        const uint32_t sbase = smem_u32p(smem);

        auto load_chunk = [&](int kc, int stage) {     // kc in 0..7
            const uint32_t aB = sbase + stage * (STG1_U32 * 4);
            const uint32_t bB = aB + A_U32 * 4;
            const float* F = (kc < 4) ? fea1 : fea2;
            const int colb = (kc & 3) * BK;
            #pragma unroll
            for (int i = 0; i < 4; i++) {
                int u  = tid + i * 256;
                int r  = u >> 3;
                int c4 = u & 7;
                int gr = block_row + r;
                if (gr >= NNODES) gr = NNODES - 1;
                cp_async16(aB + r * (SSTR * 4) + c4 * 16,
                           F + (size_t)gr * DIM + colb + c4 * 4);
            }
            #pragma unroll
            for (int i = 0; i < 4; i++) {
                int u  = tid + i * 256;
                int k  = u >> 5;
                int n4 = u & 31;
                cp_async16(bB + k * (BSTR * 4) + n4 * 16,
                           g_Wt + (size_t)(kc * BK + k) * DOUT + n4 * 4);
            }
        };

        float acc[4][4][4];
        #pragma unroll
        for (int mt = 0; mt < 4; mt++)
            #pragma unroll
            for (int nt = 0; nt < 4; nt++)
                #pragma unroll
                for (int i = 0; i < 4; i++)
                    acc[mt][nt][i] = 0.f;

        load_chunk(0, 0);
        CP_COMMIT();

        #pragma unroll 1
        for (int kc = 0; kc < 8; kc++) {
            CP_WAIT0();
            __syncthreads();
            if (kc + 1 < 8) load_chunk(kc + 1, (kc + 1) & 1);
            CP_COMMIT();

            const uint32_t* sA = smem + (kc & 1) * STG1_U32;
            const uint32_t* sB = sA + A_U32;
            #pragma unroll
            for (int ks = 0; ks < 4; ks++) {
                const int ko = ks * 8;
                uint32_t af[4][4];
                #pragma unroll
                for (int mt = 0; mt < 4; mt++) {
                    int row = warp_m + mt * 16 + gid;
                    af[mt][0] = f2tf32(__uint_as_float(sA[row * SSTR + ko + tig]));
                    af[mt][1] = f2tf32(__uint_as_float(sA[(row + 8) * SSTR + ko + tig]));
                    af[mt][2] = f2tf32(__uint_as_float(sA[row * SSTR + ko + tig + 4]));
                    af[mt][3] = f2tf32(__uint_as_float(sA[(row + 8) * SSTR + ko + tig + 4]));
                }
                uint32_t bf[4][2];
                #pragma unroll
                for (int nt = 0; nt < 4; nt++) {
                    int col = warp_n + nt * 8 + gid;
                    bf[nt][0] = sB[(ko + tig) * BSTR + col];
                    bf[nt][1] = sB[(ko + tig + 4) * BSTR + col];
                }
                #pragma unroll
                for (int mt = 0; mt < 4; mt++)
                    #pragma unroll
                    for (int nt = 0; nt < 4; nt++)
                        mma_tf32(acc[mt][nt], af[mt], bf[nt]);
            }
            __syncthreads();
        }

        // store raw fp32 partials
        #pragma unroll
        for (int mt = 0; mt < 4; mt++) {
            #pragma unroll
            for (int half = 0; half < 2; half++) {
                int gr = block_row + warp_m + mt * 16 + gid + half * 8;
                if (gr < NNODES) {
                    #pragma unroll
                    for (int nt = 0; nt < 4; nt++) {
                        float2 v;
                        v.x = acc[mt][nt][half * 2 + 0];
                        v.y = acc[mt][nt][half * 2 + 1];
                        *reinterpret_cast<float2*>(
                            g_part + (size_t)gr * DOUT + warp_n + nt * 8 + tig * 2) = v;
                    }
                }
            }
        }
    } else {
        // ================= agg role =================
        const int aid  = bid - bid / 17 - 1;          // 0..6249
        const int node = aid * 8 + (tid >> 5);        // < 50000
        const uint2* fb = reinterpret_cast<const uint2*>(g_f1b);
        const float sc = 1.0f / (float)KNEI;

        #pragma unroll
        for (int list = 0; list < 2; list++) {
            const int* idx = list ? idx2 : idx1;
            __nv_bfloat16* dst = list ? g_n2b : g_n1b;
            int myidx = idx[node * KNEI + lane];
            float4 a0 = make_float4(0.f, 0.f, 0.f, 0.f);
            float4 a1 = make_float4(0.f, 0.f, 0.f, 0.f);
            #pragma unroll
            for (int j = 0; j < KNEI; j += 2) {
                int i0 = __shfl_sync(0xffffffffu, myidx, j + 0);
                int i1 = __shfl_sync(0xffffffffu, myidx, j + 1);
                uint2 v0 = __ldg(&fb[(size_t)i0 * 32 + lane]);
                uint2 v1 = __ldg(&fb[(size_t)i1 * 32 + lane]);
                float2 l0 = __bfloat1622float2(*reinterpret_cast<__nv_bfloat162*>(&v0.x));
                float2 h0 = __bfloat1622float2(*reinterpret_cast<__nv_bfloat162*>(&v0.y));
                float2 l1 = __bfloat1622float2(*reinterpret_cast<__nv_bfloat162*>(&v1.x));
                float2 h1 = __bfloat1622float2(*reinterpret_cast<__nv_bfloat162*>(&v1.y));
                a0.x += l0.x; a0.y += l0.y; a0.z += h0.x; a0.w += h0.y;
                a1.x += l1.x; a1.y += l1.y; a1.z += h1.x; a1.w += h1.y;
            }
            __nv_bfloat162 m0 = __floats2bfloat162_rn((a0.x + a1.x) * sc, (a0.y + a1.y) * sc);
            __nv_bfloat162 m1 = __floats2bfloat162_rn((a0.z + a1.z) * sc, (a0.w + a1.w) * sc);
            uint2 o;
            o.x = *reinterpret_cast<uint32_t*>(&m0);
            o.y = *reinterpret_cast<uint32_t*>(&m1);
            *reinterpret_cast<uint2*>(&dst[(size_t)node * DIM + lane * 4]) = o;
        }
    }
}

// ---------------------------------------------------------------------------
// Kernel 3 (gemm2): out = tanh(partial + [n1|n2] @ W[256:512]).
// A is bf16 means (unpacked to tf32 via shift). 8 chunks, 2-stage pipeline.
// ---------------------------------------------------------------------------
__global__ __launch_bounds__(256, 2)
void gemm2_kernel(float* __restrict__ out) {
    extern __shared__ uint32_t smem[];

    const int tid  = threadIdx.x;
    const int wid  = tid >> 5;
    const int lane = tid & 31;
    const int gid  = lane >> 2;
    const int tig  = lane & 3;
    const int warp_m = (wid >> 2) * 64;
    const int warp_n = (wid & 3) * 32;
    const int block_row = blockIdx.x * BM;
    const uint32_t sbase = smem_u32p(smem);
    const uint32_t sel = tig & 1;

    auto load_chunk = [&](int kc, int stage) {     // kc in 0..7
        const uint32_t aB = sbase + stage * (STG2_U32 * 4);
        const uint32_t bB = aB + A2_U32 * 4;
        const __nv_bfloat16* M = (kc < 4) ? g_n1b : g_n2b;
        const int colb = (kc & 3) * BK;
        #pragma unroll
        for (int i = 0; i < 2; i++) {
            int u  = tid + i * 256;        // 0..511
            int r  = u >> 2;               // 0..127
            int c4 = u & 3;                // 0..3 (16B = 8 bf16)
            int gr = block_row + r;
            if (gr >= NNODES) gr = NNODES - 1;
            cp_async16(aB + r * (A2STR * 4) + c4 * 16,
                       M + (size_t)gr * DIM + colb + c4 * 8);
        }
        #pragma unroll
        for (int i = 0; i < 4; i++) {
            int u  = tid + i * 256;
            int k  = u >> 5;
            int n4 = u & 31;
            cp_async16(bB + k * (BSTR * 4) + n4 * 16,
                       g_Wt + (size_t)((kc + 8) * BK + k) * DOUT + n4 * 4);
        }
    };

    float acc[4][4][4];
    #pragma unroll
    for (int mt = 0; mt < 4; mt++)
        #pragma unroll
        for (int nt = 0; nt < 4; nt++)
            #pragma unroll
            for (int i = 0; i < 4; i++)
                acc[mt][nt][i] = 0.f;

    load_chunk(0, 0);
    CP_COMMIT();

    #pragma unroll 1
    for (int kc = 0; kc < 8; kc++) {
        CP_WAIT0();
        __syncthreads();
        if (kc + 1 < 8) load_chunk(kc + 1, (kc + 1) & 1);
        CP_COMMIT();

        const uint32_t* sA = smem + (kc & 1) * STG2_U32;
        const uint32_t* sB = sA + A2_U32;
        #pragma unroll
        for (int ks = 0; ks < 4; ks++) {
            const int ko = ks * 8;
            const int j0 = ks * 4 + (tig >> 1);   // u32 index holding k=ko+tig
            uint32_t af[4][4];
            #pragma unroll
            for (int mt = 0; mt < 4; mt++) {
                int row = warp_m + mt * 16 + gid;
                uint32_t v0 = sA[row * A2STR + j0];
                uint32_t v1 = sA[(row + 8) * A2STR + j0];
                uint32_t v2 = sA[row * A2STR + j0 + 2];
                uint32_t v3 = sA[(row + 8) * A2STR + j0 + 2];
                af[mt][0] = sel ? (v0 & 0xffff0000u) : (v0 << 16);
                af[mt][1] = sel ? (v1 & 0xffff0000u) : (v1 << 16);
                af[mt][2] = sel ? (v2 & 0xffff0000u) : (v2 << 16);
                af[mt][3] = sel ? (v3 & 0xffff0000u) : (v3 << 16);
            }
            uint32_t bf[4][2];
            #pragma unroll
            for (int nt = 0; nt < 4; nt++) {
                int col = warp_n + nt * 8 + gid;
                bf[nt][0] = sB[(ko + tig) * BSTR + col];
                bf[nt][1] = sB[(ko + tig + 4) * BSTR + col];
            }
            #pragma unroll
            for (int mt = 0; mt < 4; mt++)
                #pragma unroll
                for (int nt = 0; nt < 4; nt++)
                    mma_tf32(acc[mt][nt], af[mt], bf[nt]);
        }
        __syncthreads();
    }

    // epilogue: add fp32 partial, tanh, store
    #pragma unroll
    for (int mt = 0; mt < 4; mt++) {
        #pragma unroll
        for (int half = 0; half < 2; half++) {
            int gr = block_row + warp_m + mt * 16 + gid + half * 8;
            if (gr < NNODES) {
                #pragma unroll
                for (int nt = 0; nt < 4; nt++) {
                    const size_t off = (size_t)gr * DOUT + warp_n + nt * 8 + tig * 2;
                    float2 p = __ldg(reinterpret_cast<const float2*>(g_part + off));
                    float2 v;
                    v.x = tanhf(acc[mt][nt][half * 2 + 0] + p.x);
                    v.y = tanhf(acc[mt][nt][half * 2 + 1] + p.y);
                    *reinterpret_cast<float2*>(out + off) = v;
                }
            }
        }
    }
}

// ---------------------------------------------------------------------------
extern "C" void kernel_launch(void* const* d_in, const int* in_sizes, int n_in,
                              void* d_out, int out_size) {
    const float* node_fea1 = (const float*)d_in[0];
    const float* node_fea2 = (const float*)d_in[1];
    const int*   neigh1    = (const int*)  d_in[2];
    const int*   neigh2    = (const int*)  d_in[3];
    const float* weight    = (const float*)d_in[4];
    float*       out       = (float*)d_out;

    static bool attr_set = false;
    if (!attr_set) {
        cudaFuncSetAttribute(mixed_kernel,
                             cudaFuncAttributeMaxDynamicSharedMemorySize,
                             2 * STG1_U32 * 4);
        cudaFuncSetAttribute(gemm2_kernel,
                             cudaFuncAttributeMaxDynamicSharedMemorySize,
                             2 * STG2_U32 * 4);
        attr_set = true;
    }

    conv_kernel<<<(NNODES * DIM / 8 + 255) / 256, 256>>>(node_fea1, weight);

    // 391 gemm CTAs interleaved (bid%17==0) among 6250 agg CTAs
    mixed_kernel<<<6641, 256, 2 * STG1_U32 * 4>>>(node_fea1, node_fea2,
                                                  neigh1, neigh2);

    gemm2_kernel<<<(NNODES + BM - 1) / BM, 256, 2 * STG2_U32 * 4>>>(out);
}

// round 9
// speedup vs baseline: 1.2563x; 1.2563x over previous
#include <cuda_runtime.h>
#include <cuda_bf16.h>
#include <math.h>
#include <stdint.h>

#define NNODES 50000
#define KNEI   32
#define DIM    128
#define DOUT   128
#define KTOT   512
#define BM     128
#define BK     32

// smem geometry (u32 units)
#define A1STR  36                    // fp32 A row stride (144 B)
#define B1STR  136                   // tf32 B [k][n] row stride (544 B)
#define A2STR  20                    // bf16 A row stride (80 B)
#define B2STR  20                    // bf16 B [n][k] row stride (80 B)
#define B_OFF  (BM * A1STR)          // 4608: B always at stage base + this
#define STG_U32 (B_OFF + BK * B1STR) // 8960
#define NSTAGE 3

// Static device scratch (allowed).
__device__ __nv_bfloat16 g_f1b[(size_t)NNODES * DIM];   // bf16(fea1)
__device__ __nv_bfloat16 g_n1b[(size_t)NNODES * DIM];   // bf16(mean nei1)
__device__ __nv_bfloat16 g_n2b[(size_t)NNODES * DIM];   // bf16(mean nei2)
__device__ uint32_t g_Wt[(size_t)KTOT * DOUT];          // tf32(W), [k][n] (k<256 used)
__device__ __nv_bfloat16 g_Wb[(size_t)DOUT * 256];      // bf16(W[256:512]), [n][k']

__device__ __forceinline__ uint32_t f2tf32(float f) {
    uint32_t u;
    asm("cvt.rna.tf32.f32 %0, %1;" : "=r"(u) : "f"(f));
    return u;
}
__device__ __forceinline__ uint32_t smem_u32p(const void* p) {
    uint32_t a;
    asm("{ .reg .u64 t; cvta.to.shared.u64 t, %1; cvt.u32.u64 %0, t; }" : "=r"(a) : "l"(p));
    return a;
}
__device__ __forceinline__ void cp_async16(uint32_t dst, const void* src) {
    asm volatile("cp.async.cg.shared.global [%0], [%1], 16;"
                 :: "r"(dst), "l"(src) : "memory");
}
#define CP_COMMIT() asm volatile("cp.async.commit_group;" ::: "memory")
#define CP_WAIT1()  asm volatile("cp.async.wait_group 1;"  ::: "memory")

__device__ __forceinline__ void mma_tf32(float c[4], const uint32_t a[4],
                                         const uint32_t b[2]) {
    asm volatile(
        "mma.sync.aligned.m16n8k8.row.col.f32.tf32.tf32.f32 "
        "{%0,%1,%2,%3}, {%4,%5,%6,%7}, {%8,%9}, {%0,%1,%2,%3};"
        : "+f"(c[0]), "+f"(c[1]), "+f"(c[2]), "+f"(c[3])
        : "r"(a[0]), "r"(a[1]), "r"(a[2]), "r"(a[3]), "r"(b[0]), "r"(b[1]));
}
__device__ __forceinline__ void mma_bf16(float c[4], const uint32_t a[4],
                                         const uint32_t b[2]) {
    asm volatile(
        "mma.sync.aligned.m16n8k16.row.col.f32.bf16.bf16.f32 "
        "{%0,%1,%2,%3}, {%4,%5,%6,%7}, {%8,%9}, {%0,%1,%2,%3};"
        : "+f"(c[0]), "+f"(c[1]), "+f"(c[2]), "+f"(c[3])
        : "r"(a[0]), "r"(a[1]), "r"(a[2]), "r"(a[3]), "r"(b[0]), "r"(b[1]));
}

// ---------------------------------------------------------------------------
// Kernel 1 (conv): fea1 -> bf16 ; W[k<256] -> tf32 [k][n] ; W[k>=256] -> bf16 [n][k']
// ---------------------------------------------------------------------------
__global__ __launch_bounds__(256)
void conv_kernel(const float* __restrict__ fea1, const float* __restrict__ W) {
    const int t = blockIdx.x * 256 + threadIdx.x;   // 0..799999
    {
        float4 a = reinterpret_cast<const float4*>(fea1)[2 * (size_t)t];
        float4 b = reinterpret_cast<const float4*>(fea1)[2 * (size_t)t + 1];
        __nv_bfloat162 p0 = __floats2bfloat162_rn(a.x, a.y);
        __nv_bfloat162 p1 = __floats2bfloat162_rn(a.z, a.w);
        __nv_bfloat162 p2 = __floats2bfloat162_rn(b.x, b.y);
        __nv_bfloat162 p3 = __floats2bfloat162_rn(b.z, b.w);
        uint4 o;
        o.x = *reinterpret_cast<uint32_t*>(&p0);
        o.y = *reinterpret_cast<uint32_t*>(&p1);
        o.z = *reinterpret_cast<uint32_t*>(&p2);
        o.w = *reinterpret_cast<uint32_t*>(&p3);
        reinterpret_cast<uint4*>(g_f1b)[t] = o;
    }
    if (t < (256 * DOUT) / 4) {        // tf32 W, first 256 k-rows: 8192 threads x 4
        float4 w = reinterpret_cast<const float4*>(W)[t];
        uint4 o;
        o.x = f2tf32(w.x); o.y = f2tf32(w.y); o.z = f2tf32(w.z); o.w = f2tf32(w.w);
        reinterpret_cast<uint4*>(g_Wt)[t] = o;
    }
    if (t < DOUT * 128) {              // bf16 W transpose: n = t>>7, k' pair = t&127
        int n  = t >> 7;
        int kp = t & 127;              // u32 index: covers k' = 2kp, 2kp+1
        float w0 = W[(size_t)(256 + 2 * kp) * DOUT + n];
        float w1 = W[(size_t)(257 + 2 * kp) * DOUT + n];
        __nv_bfloat162 p = __floats2bfloat162_rn(w0, w1);
        reinterpret_cast<uint32_t*>(g_Wb)[n * 128 + kp] =
            *reinterpret_cast<uint32_t*>(&p);
    }
}

// ---------------------------------------------------------------------------
// Kernel 2 (agg): one warp per node; bf16 gather (256 B rows), fp32 accum,
// bf16 means out.
// ---------------------------------------------------------------------------
__global__ __launch_bounds__(256)
void agg_kernel(const int* __restrict__ idx1, const int* __restrict__ idx2) {
    const int node = blockIdx.x * 8 + (threadIdx.x >> 5);   // exact 50000
    const int lane = threadIdx.x & 31;
    const uint2* fb = reinterpret_cast<const uint2*>(g_f1b);
    const float sc = 1.0f / (float)KNEI;

    #pragma unroll
    for (int list = 0; list < 2; list++) {
        const int* idx = list ? idx2 : idx1;
        __nv_bfloat16* dst = list ? g_n2b : g_n1b;
        int myidx = idx[node * KNEI + lane];
        float4 a0 = make_float4(0.f, 0.f, 0.f, 0.f);
        float4 a1 = make_float4(0.f, 0.f, 0.f, 0.f);
        #pragma unroll
        for (int j = 0; j < KNEI; j += 2) {
            int i0 = __shfl_sync(0xffffffffu, myidx, j + 0);
            int i1 = __shfl_sync(0xffffffffu, myidx, j + 1);
            uint2 v0 = __ldg(&fb[(size_t)i0 * 32 + lane]);
            uint2 v1 = __ldg(&fb[(size_t)i1 * 32 + lane]);
            float2 l0 = __bfloat1622float2(*reinterpret_cast<__nv_bfloat162*>(&v0.x));
            float2 h0 = __bfloat1622float2(*reinterpret_cast<__nv_bfloat162*>(&v0.y));
            float2 l1 = __bfloat1622float2(*reinterpret_cast<__nv_bfloat162*>(&v1.x));
            float2 h1 = __bfloat1622float2(*reinterpret_cast<__nv_bfloat162*>(&v1.y));
            a0.x += l0.x; a0.y += l0.y; a0.z += h0.x; a0.w += h0.y;
            a1.x += l1.x; a1.y += l1.y; a1.z += h1.x; a1.w += h1.y;
        }
        __nv_bfloat162 m0 = __floats2bfloat162_rn((a0.x + a1.x) * sc, (a0.y + a1.y) * sc);
        __nv_bfloat162 m1 = __floats2bfloat162_rn((a0.z + a1.z) * sc, (a0.w + a1.w) * sc);
        uint2 o;
        o.x = *reinterpret_cast<uint32_t*>(&m0);
        o.y = *reinterpret_cast<uint32_t*>(&m1);
        *reinterpret_cast<uint2*>(&dst[(size_t)node * DIM + lane * 4]) = o;
    }
}

// ---------------------------------------------------------------------------
// Kernel 3 (gemm): out = tanh([f1|f2|n1|n2] @ W), 3-stage cp.async pipeline.
// Chunks 0..7: fp32 A (reg tf32 cvt) x tf32 B[k][n], m16n8k8.
// Chunks 8..15: bf16 A (means) x bf16 B[n][k'], m16n8k16.
// ---------------------------------------------------------------------------
__global__ __launch_bounds__(256, 2)
void gemm_kernel(const float* __restrict__ fea1,
                 const float* __restrict__ fea2,
                 float* __restrict__ out) {
    extern __shared__ uint32_t smem[];

    const int tid  = threadIdx.x;
    const int wid  = tid >> 5;
    const int lane = tid & 31;
    const int gid  = lane >> 2;
    const int tig  = lane & 3;
    const int warp_m = (wid >> 2) * 64;
    const int warp_n = (wid & 3) * 32;
    const int block_row = blockIdx.x * BM;
    const uint32_t sbase = smem_u32p(smem);

    auto load_chunk = [&](int kc, int stage) {
        const uint32_t aB = sbase + stage * (STG_U32 * 4);
        const uint32_t bB = aB + B_OFF * 4;
        if (kc < 8) {
            // fp32 A
            const float* F = (kc < 4) ? fea1 : fea2;
            const int colb = (kc & 3) * BK;
            #pragma unroll
            for (int i = 0; i < 4; i++) {
                int u  = tid + i * 256;
                int r  = u >> 3;
                int c4 = u & 7;
                int gr = block_row + r;
                if (gr >= NNODES) gr = NNODES - 1;
                cp_async16(aB + r * (A1STR * 4) + c4 * 16,
                           F + (size_t)gr * DIM + colb + c4 * 4);
            }
            // tf32 B [k][n]
            #pragma unroll
            for (int i = 0; i < 4; i++) {
                int u  = tid + i * 256;
                int k  = u >> 5;
                int n4 = u & 31;
                cp_async16(bB + k * (B1STR * 4) + n4 * 16,
                           g_Wt + (size_t)(kc * BK + k) * DOUT + n4 * 4);
            }
        } else {
            // bf16 A (means)
            const __nv_bfloat16* M = (kc < 12) ? g_n1b : g_n2b;
            const int colb = (kc & 3) * BK;   // bf16 col offset
            #pragma unroll
            for (int i = 0; i < 2; i++) {
                int u  = tid + i * 256;       // 0..511
                int r  = u >> 2;              // 0..127
                int c4 = u & 3;               // 16B = 8 bf16
                int gr = block_row + r;
                if (gr >= NNODES) gr = NNODES - 1;
                cp_async16(aB + r * (A2STR * 4) + c4 * 16,
                           M + (size_t)gr * DIM + colb + c4 * 8);
            }
            // bf16 B [n][k']: 128 rows x 32 bf16 window
            const int kp0 = ((kc - 8) * BK) / 2;   // u32 offset in g_Wb row
            #pragma unroll
            for (int i = 0; i < 2; i++) {
                int u  = tid + i * 256;
                int r  = u >> 2;              // n = 0..127
                int c4 = u & 3;
                cp_async16(bB + r * (B2STR * 4) + c4 * 16,
                           reinterpret_cast<const uint32_t*>(g_Wb) +
                               (size_t)r * 128 + kp0 + c4 * 4);
            }
        }
    };

    float acc[4][4][4];
    #pragma unroll
    for (int mt = 0; mt < 4; mt++)
        #pragma unroll
        for (int nt = 0; nt < 4; nt++)
            #pragma unroll
            for (int i = 0; i < 4; i++)
                acc[mt][nt][i] = 0.f;

    // prologue: 2 chunks in flight
    load_chunk(0, 0);
    CP_COMMIT();
    load_chunk(1, 1);
    CP_COMMIT();

    #pragma unroll 1
    for (int kc = 0; kc < 16; kc++) {
        CP_WAIT1();                       // chunk kc landed
        __syncthreads();                  // stage (kc+2)%3 free (read in kc-1)
        if (kc + 2 < 16) load_chunk(kc + 2, (kc + 2) % NSTAGE);
        CP_COMMIT();

        const uint32_t* sA = smem + (kc % NSTAGE) * STG_U32;
        const uint32_t* sB = sA + B_OFF;

        if (kc < 8) {
            #pragma unroll
            for (int ks = 0; ks < 4; ks++) {
                const int ko = ks * 8;
                uint32_t af[4][4];
                #pragma unroll
                for (int mt = 0; mt < 4; mt++) {
                    int row = warp_m + mt * 16 + gid;
                    af[mt][0] = f2tf32(__uint_as_float(sA[row * A1STR + ko + tig]));
                    af[mt][1] = f2tf32(__uint_as_float(sA[(row + 8) * A1STR + ko + tig]));
                    af[mt][2] = f2tf32(__uint_as_float(sA[row * A1STR + ko + tig + 4]));
                    af[mt][3] = f2tf32(__uint_as_float(sA[(row + 8) * A1STR + ko + tig + 4]));
                }
                uint32_t bf[4][2];
                #pragma unroll
                for (int nt = 0; nt < 4; nt++) {
                    int col = warp_n + nt * 8 + gid;
                    bf[nt][0] = sB[(ko + tig) * B1STR + col];
                    bf[nt][1] = sB[(ko + tig + 4) * B1STR + col];
                }
                #pragma unroll
                for (int mt = 0; mt < 4; mt++)
                    #pragma unroll
                    for (int nt = 0; nt < 4; nt++)
                        mma_tf32(acc[mt][nt], af[mt], bf[nt]);
            }
        } else {
            #pragma unroll
            for (int ks = 0; ks < 2; ks++) {      // 2 x k16
                const int j = ks * 8;             // u32 offset (16 bf16)
                uint32_t af[4][4];
                #pragma unroll
                for (int mt = 0; mt < 4; mt++) {
                    int row = warp_m + mt * 16 + gid;
                    af[mt][0] = sA[row * A2STR + j + tig];
                    af[mt][1] = sA[(row + 8) * A2STR + j + tig];
                    af[mt][2] = sA[row * A2STR + j + tig + 4];
                    af[mt][3] = sA[(row + 8) * A2STR + j + tig + 4];
                }
                uint32_t bf[4][2];
                #pragma unroll
                for (int nt = 0; nt < 4; nt++) {
                    int col = warp_n + nt * 8 + gid;
                    bf[nt][0] = sB[col * B2STR + j + tig];
                    bf[nt][1] = sB[col * B2STR + j + tig + 4];
                }
                #pragma unroll
                for (int mt = 0; mt < 4; mt++)
                    #pragma unroll
                    for (int nt = 0; nt < 4; nt++)
                        mma_bf16(acc[mt][nt], af[mt], bf[nt]);
            }
        }
        __syncthreads();
    }

    // epilogue: tanh + store
    #pragma unroll
    for (int mt = 0; mt < 4; mt++) {
        #pragma unroll
        for (int half = 0; half < 2; half++) {
            int gr = block_row + warp_m + mt * 16 + gid + half * 8;
            if (gr < NNODES) {
                #pragma unroll
                for (int nt = 0; nt < 4; nt++) {
                    float2 v;
                    v.x = tanhf(acc[mt][nt][half * 2 + 0]);
                    v.y = tanhf(acc[mt][nt][half * 2 + 1]);
                    *reinterpret_cast<float2*>(
                        out + (size_t)gr * DOUT + warp_n + nt * 8 + tig * 2) = v;
                }
            }
        }
    }
}

// ---------------------------------------------------------------------------
extern "C" void kernel_launch(void* const* d_in, const int* in_sizes, int n_in,
                              void* d_out, int out_size) {
    const float* node_fea1 = (const float*)d_in[0];
    const float* node_fea2 = (const float*)d_in[1];
    const int*   neigh1    = (const int*)  d_in[2];
    const int*   neigh2    = (const int*)  d_in[3];
    const float* weight    = (const float*)d_in[4];
    float*       out       = (float*)d_out;

    const int dyn_smem = NSTAGE * STG_U32 * 4;   // 107520 B
    static bool attr_set = false;
    if (!attr_set) {
        cudaFuncSetAttribute(gemm_kernel,
                             cudaFuncAttributeMaxDynamicSharedMemorySize, dyn_smem);
        attr_set = true;
    }

    conv_kernel<<<(NNODES * DIM / 8 + 255) / 256, 256>>>(node_fea1, weight);
    agg_kernel<<<NNODES / 8, 256>>>(neigh1, neigh2);
    gemm_kernel<<<(NNODES + BM - 1) / BM, 256, dyn_smem>>>(node_fea1, node_fea2, out);
}